// round 8
// baseline (speedup 1.0000x reference)
#include <cuda_runtime.h>
#include <cstdint>

// ============================================================================
// out = adj @ (x @ W)
//   x   [16384, 2048] f32  (d_in[0])
//   adj [16384,16384] f32  (d_in[1])
//   W   [ 2048,  512] f32  (d_in[2])
//   out [16384,  512] f32
//
// tf32 mma.sync GEMM, 64x64 warp tiles (4 warps, CTA 128x128).
// Round 8: 3 CTAs/SM (3 warps/SMSP for latency hiding) => 2-stage cp.async
// pipeline (smem 73.7KB/CTA) + single-buffered fragments (regs <= 170).
// GEMM1 writes hT[512][16384] (transposed, tf32-pre-rounded); GEMM2 loads
// both operands k-major and uses ldmatrix.x4 for A and B fragments.
// ============================================================================

#define BM 128
#define BN 128
#define BK 32
#define NTHREADS 128
#define NCOLS 512
#define NROWS 16384
#define SA 36                  // k-major tile row stride (floats): 32 + 4 pad
#define SBKN 136               // GEMM1 B [k][n] row stride: 128 + 8 pad
#define NSTAGE 2

static constexpr int A_STAGE_F = BM * SA;                   // 4608 floats

__device__ float g_hT[(size_t)NCOLS * NROWS];               // 32 MB scratch (h^T)

__device__ __forceinline__ uint32_t f2tf(float f) {
    uint32_t u;
    asm("cvt.rna.tf32.f32 %0, %1;" : "=r"(u) : "f"(f));
    return u;
}
__device__ __forceinline__ uint32_t f2tf_u(uint32_t x) {
    return f2tf(__uint_as_float(x));
}

__device__ __forceinline__ uint32_t smem_u32(const void* p) {
    uint32_t a;
    asm("{ .reg .u64 t; cvta.to.shared.u64 t, %1; cvt.u32.u64 %0, t; }"
        : "=r"(a) : "l"(p));
    return a;
}

__device__ __forceinline__ void cp_async16(uint32_t dst, const void* src) {
    asm volatile("cp.async.cg.shared.global [%0], [%1], 16;"
                 :: "r"(dst), "l"(src));
}
__device__ __forceinline__ void cp_commit() {
    asm volatile("cp.async.commit_group;");
}
template <int N>
__device__ __forceinline__ void cp_wait() {
    asm volatile("cp.async.wait_group %0;" :: "n"(N));
}

__device__ __forceinline__ void ldsm_x4(uint32_t* r, uint32_t addr) {
    asm volatile(
        "ldmatrix.sync.aligned.m8n8.x4.shared.b16 {%0,%1,%2,%3}, [%4];"
        : "=r"(r[0]), "=r"(r[1]), "=r"(r[2]), "=r"(r[3]) : "r"(addr));
}

__device__ __forceinline__ void mma_tf32(float* d,
                                         const uint32_t* a,
                                         const uint32_t* b) {
    asm volatile(
        "mma.sync.aligned.m16n8k8.row.col.f32.tf32.tf32.f32 "
        "{%0,%1,%2,%3}, {%4,%5,%6,%7}, {%8,%9}, {%0,%1,%2,%3};"
        : "+f"(d[0]), "+f"(d[1]), "+f"(d[2]), "+f"(d[3])
        : "r"(a[0]), "r"(a[1]), "r"(a[2]), "r"(a[3]),
          "r"(b[0]), "r"(b[1]));
}

// SECOND=false: GEMM1  h^T = (A@B)^T, B=[k][n] scalar-LDS frags, cvt both,
//               tf32-rounded transposed epilogue (C[n*ldC+m]).
// SECOND=true : GEMM2  C = A@B^T with B=hT[n][k] k-major, ldmatrix A & B,
//               cvt A only, row-major float2 epilogue.
template <bool SECOND>
__global__ void __launch_bounds__(NTHREADS, 3)
gemm_tf32_kernel(const float* __restrict__ A, const float* __restrict__ B,
                 float* __restrict__ C, int K, int ldB, int ldC) {
    constexpr int B_STAGE_F = SECOND ? (BN * SA) : (BK * SBKN);
    constexpr int STAGE_F   = A_STAGE_F + B_STAGE_F;

    extern __shared__ float smem[];

    const int tid  = threadIdx.x;
    const int wid  = tid >> 5;           // 0..3
    const int lane = tid & 31;
    const int q    = lane >> 2;          // 0..7
    const int t    = lane & 3;           // 0..3

    const int m0 = blockIdx.y * BM;
    const int n0 = blockIdx.x * BN;
    const int wm = (wid & 1) * 64;       // 2x2 warp grid, 64x64 warp tiles
    const int wn = (wid >> 1) * 64;

    const uint32_t smem_base = smem_u32(smem);

    // ---- cp.async fill addressing ----
    const float* a_src = A + (size_t)(m0 + (tid >> 3)) * K + (tid & 7) * 4;
    const uint32_t a_dst = smem_base + ((tid >> 3) * SA + (tid & 7) * 4) * 4;

    const float* b_src;
    uint32_t b_dst;
    if (SECOND) {   // hT rows: n-major, k-contiguous — same shape as A tile
        b_src = B + (size_t)(n0 + (tid >> 3)) * ldB + (tid & 7) * 4;
        b_dst = smem_base + (A_STAGE_F + (tid >> 3) * SA + (tid & 7) * 4) * 4;
    } else {        // W rows: k-major over n
        b_src = B + (size_t)(tid >> 5) * ldB + n0 + (tid & 31) * 4;
        b_dst = smem_base + (A_STAGE_F + (tid >> 5) * SBKN + (tid & 31) * 4) * 4;
    }

    const int niter = K / BK;

    auto issue = [&](int sbuf, int kb) {
        const uint32_t soff = (uint32_t)(sbuf * STAGE_F * 4);
        const float* as = a_src + (size_t)kb * BK;
        #pragma unroll
        for (int i = 0; i < 8; ++i)
            cp_async16(a_dst + soff + i * (16 * SA * 4), as + (size_t)i * 16 * K);
        if (SECOND) {
            const float* bs = b_src + (size_t)kb * BK;
            #pragma unroll
            for (int i = 0; i < 8; ++i)
                cp_async16(b_dst + soff + i * (16 * SA * 4), bs + (size_t)i * 16 * ldB);
        } else {
            const float* bs = b_src + (size_t)kb * BK * ldB;
            #pragma unroll
            for (int i = 0; i < 8; ++i)
                cp_async16(b_dst + soff + i * (4 * SBKN * 4), bs + (size_t)i * 4 * ldB);
        }
    };

    float acc[4][8][4];
    #pragma unroll
    for (int i = 0; i < 4; ++i)
        #pragma unroll
        for (int j = 0; j < 8; ++j)
            #pragma unroll
            for (int r = 0; r < 4; ++r)
                acc[i][j][r] = 0.0f;

    // prologue: stage 0 in flight
    issue(0, 0); cp_commit();

    // A ldmatrix lane addressing: row = wm + mi*16 + (lane&15), col4 = (lane>>4)*4
    const uint32_t a_lds = smem_base +
        (((wm + (lane & 15)) * SA + (lane >> 4) * 4) * 4);
    // B (SECOND) ldmatrix: tile j covers ni=2j,2j+1:
    //   row = wn + 16j + 8*(lane>>4) + (lane&7), col4 = ((lane>>3)&1)*4
    const uint32_t b_lds = smem_base +
        ((A_STAGE_F + (wn + 8 * (lane >> 4) + (lane & 7)) * SA
          + ((lane >> 3) & 1) * 4) * 4);
    // B (GEMM1) scalar frag base
    const int boff = A_STAGE_F + t * SBKN + wn + q;

    // single-buffered fragments (regs: keep <=170 for 3 CTAs/SM)
    uint32_t af[4][4];
    uint32_t bf[8][2];

    for (int it = 0; it < niter; ++it) {
        const int buf = it & 1;

        cp_wait<0>();                 // stage `it` resident
        __syncthreads();              // prior reads of buf^1 complete

        // stage it+1 into the other buffer; overlaps all of this iter's math
        if (it + 1 < niter) issue(buf ^ 1, it + 1);
        cp_commit();

        const uint32_t soff    = (uint32_t)(buf * STAGE_F * 4);
        const uint32_t a_stage = a_lds + soff;
        const uint32_t b_stage = b_lds + soff;
        const float*   Bc      = smem + buf * STAGE_F;

        #pragma unroll
        for (int k8 = 0; k8 < 4; ++k8) {
            if (SECOND) {
                #pragma unroll
                for (int j = 0; j < 4; ++j) {
                    uint32_t r[4];
                    ldsm_x4(r, b_stage + (uint32_t)((j * 16 * SA + k8 * 8) * 4));
                    bf[2 * j][0]     = r[0];
                    bf[2 * j][1]     = r[1];
                    bf[2 * j + 1][0] = r[2];
                    bf[2 * j + 1][1] = r[3];
                }
            } else {
                #pragma unroll
                for (int ni = 0; ni < 8; ++ni) {
                    const float* bb = Bc + boff + k8 * (8 * SBKN) + ni * 8;
                    bf[ni][0] = f2tf(bb[0]);
                    bf[ni][1] = f2tf(bb[4 * SBKN]);
                }
            }
            #pragma unroll
            for (int mi = 0; mi < 4; ++mi) {
                ldsm_x4(af[mi], a_stage + (uint32_t)((mi * 16 * SA + k8 * 8) * 4));
                af[mi][0] = f2tf_u(af[mi][0]);
                af[mi][1] = f2tf_u(af[mi][1]);
                af[mi][2] = f2tf_u(af[mi][2]);
                af[mi][3] = f2tf_u(af[mi][3]);
            }
            #pragma unroll
            for (int mi = 0; mi < 4; ++mi)
                #pragma unroll
                for (int ni = 0; ni < 8; ++ni)
                    mma_tf32(acc[mi][ni], af[mi], bf[ni]);
        }
    }

    // ---- epilogue ----
    #pragma unroll
    for (int mi = 0; mi < 4; ++mi) {
        #pragma unroll
        for (int ni = 0; ni < 8; ++ni) {
            const int m = m0 + wm + mi * 16 + q;
            const int n = n0 + wn + ni * 8 + 2 * t;
            if (SECOND) {
                *(float2*)(C + (size_t)m * ldC + n) =
                    make_float2(acc[mi][ni][0], acc[mi][ni][1]);
                *(float2*)(C + (size_t)(m + 8) * ldC + n) =
                    make_float2(acc[mi][ni][2], acc[mi][ni][3]);
            } else {
                // write h^T, tf32-pre-rounded: C[n*ldC + m]
                C[(size_t)n * ldC + m] =
                    __uint_as_float(f2tf(acc[mi][ni][0]));
                C[(size_t)(n + 1) * ldC + m] =
                    __uint_as_float(f2tf(acc[mi][ni][1]));
                C[(size_t)n * ldC + m + 8] =
                    __uint_as_float(f2tf(acc[mi][ni][2]));
                C[(size_t)(n + 1) * ldC + m + 8] =
                    __uint_as_float(f2tf(acc[mi][ni][3]));
            }
        }
    }
}

// ---------------------------------------------------------------------------
extern "C" void kernel_launch(void* const* d_in, const int* in_sizes, int n_in,
                              void* d_out, int out_size) {
    const float* x   = (const float*)d_in[0];   // [16384, 2048]
    const float* adj = (const float*)d_in[1];   // [16384, 16384]
    const float* W   = (const float*)d_in[2];   // [2048, 512]
    float* out = (float*)d_out;                 // [16384, 512]

    float* hT;
    cudaGetSymbolAddress((void**)&hT, g_hT);

    constexpr int SMEM1 = NSTAGE * (A_STAGE_F + BK * SBKN) * 4;  // 71680
    constexpr int SMEM2 = NSTAGE * (A_STAGE_F + BN * SA) * 4;    // 73728

    cudaFuncSetAttribute(gemm_tf32_kernel<false>,
                         cudaFuncAttributeMaxDynamicSharedMemorySize, SMEM1);
    cudaFuncSetAttribute(gemm_tf32_kernel<true>,
                         cudaFuncAttributeMaxDynamicSharedMemorySize, SMEM2);

    dim3 grid(NCOLS / BN, NROWS / BM);   // (4, 128)

    // hT = round_tf32((x @ W)^T)
    gemm_tf32_kernel<false><<<grid, NTHREADS, SMEM1>>>(
        x, W, hT, 2048, NCOLS, NROWS);
    // out = adj @ hT^T  (A and B fragments both via ldmatrix)
    gemm_tf32_kernel<true><<<grid, NTHREADS, SMEM2>>>(
        adj, hT, out, NROWS, NROWS, NCOLS);
}

// round 9
// speedup vs baseline: 1.2978x; 1.2978x over previous
#include <cuda_runtime.h>
#include <cstdint>

// ============================================================================
// out = adj @ (x @ W)
//   x   [16384, 2048] f32  (d_in[0])
//   adj [16384,16384] f32  (d_in[1])
//   W   [ 2048,  512] f32  (d_in[2])
//   out [16384,  512] f32
//
// tf32 mma.sync GEMM, 64x64 warp tiles (4 warps, CTA 128x128), cp.async
// 3-stage pipeline, frag double-buffering, 2 CTAs/SM.  (R6 base.)
// Round 9 change: fragment loads issue FIRST after the barrier; the stage
// it+2 cp.asyncs are interleaved in 4-chunk groups after each k8 MMA block,
// so critical-path LDS/LDSM never queue behind a 16-deep LSU burst.
// h written tf32-pre-rounded by GEMM1 so GEMM2 skips B cvt.
// ============================================================================

#define BM 128
#define BN 128
#define BK 32
#define NTHREADS 128
#define NCOLS 512
#define SA 36                  // A smem row stride (floats): 32 + 4 pad
#define SB 136                 // B smem row stride (floats): 128 + 8 pad (conflict-free)
#define NSTAGE 3

static constexpr int A_STAGE_F   = BM * SA;                 // 4608 floats
static constexpr int B_STAGE_F   = BK * SB;                 // 4352 floats
static constexpr int STAGE_F     = A_STAGE_F + B_STAGE_F;   // 8960 floats
static constexpr int SMEM_BYTES  = NSTAGE * STAGE_F * 4;    // 107520 B

__device__ float g_h[(size_t)16384 * NCOLS];                // 32 MB scratch

__device__ __forceinline__ uint32_t f2tf(float f) {
    uint32_t u;
    asm("cvt.rna.tf32.f32 %0, %1;" : "=r"(u) : "f"(f));
    return u;
}
__device__ __forceinline__ uint32_t f2tf_u(uint32_t x) {
    return f2tf(__uint_as_float(x));
}

__device__ __forceinline__ uint32_t smem_u32(const void* p) {
    uint32_t a;
    asm("{ .reg .u64 t; cvta.to.shared.u64 t, %1; cvt.u32.u64 %0, t; }"
        : "=r"(a) : "l"(p));
    return a;
}

__device__ __forceinline__ void cp_async16(uint32_t dst, const void* src) {
    asm volatile("cp.async.cg.shared.global [%0], [%1], 16;"
                 :: "r"(dst), "l"(src));
}
__device__ __forceinline__ void cp_commit() {
    asm volatile("cp.async.commit_group;");
}
template <int N>
__device__ __forceinline__ void cp_wait() {
    asm volatile("cp.async.wait_group %0;" :: "n"(N));
}

__device__ __forceinline__ void ldsm_x4(uint32_t* r, uint32_t addr) {
    asm volatile(
        "ldmatrix.sync.aligned.m8n8.x4.shared.b16 {%0,%1,%2,%3}, [%4];"
        : "=r"(r[0]), "=r"(r[1]), "=r"(r[2]), "=r"(r[3]) : "r"(addr));
}

__device__ __forceinline__ void mma_tf32(float* d,
                                         const uint32_t* a,
                                         const uint32_t* b) {
    asm volatile(
        "mma.sync.aligned.m16n8k8.row.col.f32.tf32.tf32.f32 "
        "{%0,%1,%2,%3}, {%4,%5,%6,%7}, {%8,%9}, {%0,%1,%2,%3};"
        : "+f"(d[0]), "+f"(d[1]), "+f"(d[2]), "+f"(d[3])
        : "r"(a[0]), "r"(a[1]), "r"(a[2]), "r"(a[3]),
          "r"(b[0]), "r"(b[1]));
}

template <bool CVT_A, bool CVT_B, bool ROUND_OUT>
__global__ void __launch_bounds__(NTHREADS, 2)
gemm_tf32_kernel(const float* __restrict__ A, const float* __restrict__ B,
                 float* __restrict__ C, int K) {
    extern __shared__ float smem[];

    const int tid  = threadIdx.x;
    const int wid  = tid >> 5;           // 0..3
    const int lane = tid & 31;
    const int q    = lane >> 2;          // 0..7
    const int t    = lane & 3;           // 0..3

    const int m0 = blockIdx.y * BM;
    const int n0 = blockIdx.x * BN;
    const int wm = (wid & 1) * 64;       // 2x2 warp grid, 64x64 warp tiles
    const int wn = (wid >> 1) * 64;

    const float* a_src = A + (size_t)(m0 + (tid >> 3)) * K + (tid & 7) * 4;
    const float* b_src = B + (size_t)(tid >> 5) * NCOLS + n0 + (tid & 31) * 4;
    const uint32_t smem_base = smem_u32(smem);
    const uint32_t a_dst = smem_base + ((tid >> 3) * SA + (tid & 7) * 4) * 4;
    const uint32_t b_dst = smem_base + (A_STAGE_F + (tid >> 5) * SB + (tid & 31) * 4) * 4;

    const int niter = K / BK;

    // one quarter of a stage's loads: part 0/1 = A halves, part 2/3 = B halves
    auto issue_chunk = [&](int sbuf, int kb, int part) {
        const uint32_t soff = (uint32_t)(sbuf * STAGE_F * 4);
        if (part < 2) {
            const float* as = a_src + (size_t)kb * BK;
            #pragma unroll
            for (int i = 0; i < 4; ++i) {
                int c = part * 4 + i;
                cp_async16(a_dst + soff + c * (16 * SA * 4), as + (size_t)c * 16 * K);
            }
        } else {
            const float* bs = b_src + (size_t)kb * BK * NCOLS;
            #pragma unroll
            for (int i = 0; i < 4; ++i) {
                int c = (part - 2) * 4 + i;
                cp_async16(b_dst + soff + c * (4 * SB * 4), bs + (size_t)c * 4 * NCOLS);
            }
        }
    };
    auto issue_all = [&](int sbuf, int kb) {
        #pragma unroll
        for (int p = 0; p < 4; ++p) issue_chunk(sbuf, kb, p);
    };

    float acc[4][8][4];
    #pragma unroll
    for (int i = 0; i < 4; ++i)
        #pragma unroll
        for (int j = 0; j < 8; ++j)
            #pragma unroll
            for (int r = 0; r < 4; ++r)
                acc[i][j][r] = 0.0f;

    issue_all(0, 0); cp_commit();
    issue_all(1, 1); cp_commit();

    // ldmatrix lane addressing: row = wm + mi*16 + (lane&15), col4 = (lane>>4)*4
    const uint32_t a_lds = smem_base +
        (((wm + (lane & 15)) * SA + (lane >> 4) * 4) * 4);
    const int boff = A_STAGE_F + t * SB + wn + q;

    uint32_t af[2][4][4];
    uint32_t bf[2][8][2];

    int buf = 0;
    for (int it = 0; it < niter; ++it) {
        cp_wait<1>();
        __syncthreads();

        const uint32_t a_stage = a_lds + (uint32_t)(buf * STAGE_F * 4);
        const float*   Bc      = smem + buf * STAGE_F;

        auto load_frags = [&](int k, int pb) {
            #pragma unroll
            for (int mi = 0; mi < 4; ++mi) {
                ldsm_x4(af[pb][mi], a_stage + (uint32_t)((mi * 16 * SA + k * 8) * 4));
                if (CVT_A) {
                    af[pb][mi][0] = f2tf_u(af[pb][mi][0]);
                    af[pb][mi][1] = f2tf_u(af[pb][mi][1]);
                    af[pb][mi][2] = f2tf_u(af[pb][mi][2]);
                    af[pb][mi][3] = f2tf_u(af[pb][mi][3]);
                }
            }
            #pragma unroll
            for (int ni = 0; ni < 8; ++ni) {
                const float* bb = Bc + boff + k * (8 * SB) + ni * 8;
                if (CVT_B) {
                    bf[pb][ni][0] = f2tf(bb[0]);
                    bf[pb][ni][1] = f2tf(bb[4 * SB]);
                } else {
                    bf[pb][ni][0] = ((const uint32_t*)bb)[0];
                    bf[pb][ni][1] = ((const uint32_t*)bb)[4 * SB];
                }
            }
        };

        // critical path first: k8=0 fragments hit an empty MIO queue
        load_frags(0, 0);

        const bool do_issue = (it + 2 < niter);
        int nb = buf + 2; if (nb >= NSTAGE) nb -= NSTAGE;

        #pragma unroll
        for (int k8 = 0; k8 < 4; ++k8) {
            const int cur = k8 & 1;
            if (k8 < 3) load_frags(k8 + 1, cur ^ 1);
            #pragma unroll
            for (int mi = 0; mi < 4; ++mi)
                #pragma unroll
                for (int ni = 0; ni < 8; ++ni)
                    mma_tf32(acc[mi][ni], af[cur][mi], bf[cur][ni]);
            // interleave a quarter of next-next stage's loads behind the MMAs
            if (do_issue) issue_chunk(nb, it + 2, k8);
        }
        cp_commit();

        if (++buf >= NSTAGE) buf = 0;
    }

    // ---- epilogue: row-major C, float2 stores ----
    #pragma unroll
    for (int mi = 0; mi < 4; ++mi) {
        #pragma unroll
        for (int ni = 0; ni < 8; ++ni) {
            const int m = m0 + wm + mi * 16 + q;
            const int n = n0 + wn + ni * 8 + 2 * t;
            float v0 = acc[mi][ni][0], v1 = acc[mi][ni][1];
            float v2 = acc[mi][ni][2], v3 = acc[mi][ni][3];
            if (ROUND_OUT) {
                v0 = __uint_as_float(f2tf(v0));
                v1 = __uint_as_float(f2tf(v1));
                v2 = __uint_as_float(f2tf(v2));
                v3 = __uint_as_float(f2tf(v3));
            }
            *(float2*)(C + (size_t)m * NCOLS + n)       = make_float2(v0, v1);
            *(float2*)(C + (size_t)(m + 8) * NCOLS + n) = make_float2(v2, v3);
        }
    }
}

// ---------------------------------------------------------------------------
extern "C" void kernel_launch(void* const* d_in, const int* in_sizes, int n_in,
                              void* d_out, int out_size) {
    const float* x   = (const float*)d_in[0];   // [16384, 2048]
    const float* adj = (const float*)d_in[1];   // [16384, 16384]
    const float* W   = (const float*)d_in[2];   // [2048, 512]
    float* out = (float*)d_out;                 // [16384, 512]

    float* h;
    cudaGetSymbolAddress((void**)&h, g_h);

    cudaFuncSetAttribute(gemm_tf32_kernel<true, true, true>,
                         cudaFuncAttributeMaxDynamicSharedMemorySize, SMEM_BYTES);
    cudaFuncSetAttribute(gemm_tf32_kernel<true, false, false>,
                         cudaFuncAttributeMaxDynamicSharedMemorySize, SMEM_BYTES);

    dim3 grid(NCOLS / BN, 16384 / BM);   // (4, 128)

    // h = round_tf32(x @ W)
    gemm_tf32_kernel<true, true, true><<<grid, NTHREADS, SMEM_BYTES>>>(
        x, W, h, 2048);
    // out = adj @ h   (h already tf32: no B cvt)
    gemm_tf32_kernel<true, false, false><<<grid, NTHREADS, SMEM_BYTES>>>(
        adj, h, out, 16384);
}